// round 2
// baseline (speedup 1.0000x reference)
#include <cuda_runtime.h>

#define LL 12
#define BB 4
#define CC 768
#define HWN 256
#define DD 128
#define NMAX 30000

// ---------------- device scratch (no allocations allowed) ----------------
__device__ float g_feat[LL * BB * DD * HWN];     // [l][b][d][hw]
__device__ float g_part[LL * BB * NMAX];         // per-layer local partial dot
__device__ float g_sel_layer[NMAX * LL];
__device__ float g_sel_scale[NMAX];
__device__ float g_corner[NMAX * 4];             // x0f, y0f, wx, wy
__device__ float g_gb[LL * BB * DD];
__device__ float g_ent_part[2048];
__device__ float g_sq_part[2048];

__device__ __forceinline__ float gelu_exact(float x) {
    return 0.5f * x * (1.0f + erff(x * 0.70710678118654752440f));
}
__device__ __forceinline__ float wred(float v) {
#pragma unroll
    for (int o = 16; o; o >>= 1) v += __shfl_xor_sync(0xffffffffu, v, o);
    return v;
}

// ---------------- K1: gb[l,b,d] = sum_c gt[l,b,c] * gw[l,d,c] ----------------
__global__ void k_gb(const float* __restrict__ gt, const float* __restrict__ gw) {
    __shared__ float gts[CC];
    int lb = blockIdx.x;  // l*BB + b
    for (int i = threadIdx.x; i < CC; i += blockDim.x) gts[i] = gt[lb * CC + i];
    __syncthreads();
    int d = threadIdx.x;  // 128 threads
    int l = lb >> 2;
    const float4* w4 = (const float4*)(gw + (size_t)(l * DD + d) * CC);
    const float4* t4 = (const float4*)gts;
    float acc = 0.f;
#pragma unroll 8
    for (int c4 = 0; c4 < CC / 4; c4++) {
        float4 w = w4[c4];
        float4 t = t4[c4];
        acc += w.x * t.x + w.y * t.y + w.z * t.z + w.w * t.w;
    }
    g_gb[lb * DD + d] = acc;
}

// ---------------- K2: selector MLPs (3 heads), 64 points per block ----------------
// smem: Ws (24576 f) | pe/h2 (12288 f) | h1 (64*132 f)
#define SEL_W_F   (192 * DD)
#define SEL_PE_F  (64 * 192)
#define SEL_H_F   (64 * 132)
#define SEL_SMEM_BYTES ((SEL_W_F + SEL_PE_F + SEL_H_F) * 4)

__global__ void k_sel(const float* __restrict__ coords,
                      const float* __restrict__ W1, const float* __restrict__ b1,
                      const float* __restrict__ W2, const float* __restrict__ b2,
                      const float* __restrict__ w3s, const float* __restrict__ w3l,
                      const float* __restrict__ w3c, int N) {
    extern __shared__ float sm[];
    float* Ws   = sm;                       // W1 then W2
    float* peh2 = sm + SEL_W_F;             // pe [64][192], later h2 [64][132]
    float* h1   = sm + SEL_W_F + SEL_PE_F;  // [64][132]
    __shared__ float redbuf[8];

    const int head = blockIdx.y;
    const int base = blockIdx.x * 64;
    const int tid = threadIdx.x;

    // load W1 [192][128]
    const float* W1p = W1 + head * 192 * DD;
    for (int i = tid; i < 192 * DD; i += 256) Ws[i] = W1p[i];
    // positional encoding
    for (int idx = tid; idx < 64 * 192; idx += 256) {
        int p = idx / 192, i = idx - p * 192;
        int n = base + p;
        float v = 0.f;
        if (n < N) {
            int c = i >> 6;
            int t = i & 63;
            int k = t & 31;
            float f = 3.14159265358979323846f * exp2f((float)k * (8.0f / 31.0f));
            float ang = coords[n * 3 + c] * f;
            v = (t < 32) ? sinf(ang) : cosf(ang);
        }
        peh2[idx] = v;
    }
    __syncthreads();

    const int tx = tid & 31, ty = tid >> 5;
    const int j0 = tx * 4, p0 = ty * 8;
    float acc[8][4];
#pragma unroll
    for (int p = 0; p < 8; p++)
#pragma unroll
        for (int q = 0; q < 4; q++) acc[p][q] = 0.f;

    // GEMM1: [64 x 192] @ [192 x 128]
    for (int i = 0; i < 192; i++) {
        float4 w = *(const float4*)&Ws[i * DD + j0];
#pragma unroll
        for (int p = 0; p < 8; p++) {
            float pv = peh2[(p0 + p) * 192 + i];
            acc[p][0] += pv * w.x;
            acc[p][1] += pv * w.y;
            acc[p][2] += pv * w.z;
            acc[p][3] += pv * w.w;
        }
    }
    {
        float4 bv = *(const float4*)&b1[head * DD + j0];
#pragma unroll
        for (int p = 0; p < 8; p++) {
            float4 h;
            h.x = gelu_exact(acc[p][0] + bv.x);
            h.y = gelu_exact(acc[p][1] + bv.y);
            h.z = gelu_exact(acc[p][2] + bv.z);
            h.w = gelu_exact(acc[p][3] + bv.w);
            *(float4*)&h1[(p0 + p) * 132 + j0] = h;
        }
    }
    __syncthreads();
    // load W2 [128][128] over W1
    const float* W2p = W2 + head * DD * DD;
    for (int i = tid; i < DD * DD; i += 256) Ws[i] = W2p[i];
    __syncthreads();

#pragma unroll
    for (int p = 0; p < 8; p++)
#pragma unroll
        for (int q = 0; q < 4; q++) acc[p][q] = 0.f;
    // GEMM2: [64 x 128] @ [128 x 128]
    for (int i = 0; i < DD; i++) {
        float4 w = *(const float4*)&Ws[i * DD + j0];
#pragma unroll
        for (int p = 0; p < 8; p++) {
            float pv = h1[(p0 + p) * 132 + i];
            acc[p][0] += pv * w.x;
            acc[p][1] += pv * w.y;
            acc[p][2] += pv * w.z;
            acc[p][3] += pv * w.w;
        }
    }
    {
        float4 bv = *(const float4*)&b2[head * DD + j0];
#pragma unroll
        for (int p = 0; p < 8; p++) {
            float4 h;
            h.x = gelu_exact(acc[p][0] + bv.x);
            h.y = gelu_exact(acc[p][1] + bv.y);
            h.z = gelu_exact(acc[p][2] + bv.z);
            h.w = gelu_exact(acc[p][3] + bv.w);
            *(float4*)&peh2[(p0 + p) * 132 + j0] = h;  // h2 tile
        }
    }
    __syncthreads();

    // phase3: one thread per point (threads 0..63)
    float redv = 0.f;
    if (tid < 64) {
        int n = base + tid;
        if (n < N) {
            const float* h2 = &peh2[tid * 132];
            if (head == 0) {
                float o0 = 0.f, o1 = 0.f;
                for (int j = 0; j < DD; j++) {
                    float h = h2[j];
                    o0 += h * w3s[j * 2 + 0];
                    o1 += h * w3s[j * 2 + 1];
                }
                float sx = tanhf(o0), sy = tanhf(o1);
                float xf = (sx + 1.f) * 8.f - 0.5f;
                float yf = (sy + 1.f) * 8.f - 0.5f;
                float x0 = floorf(xf), y0 = floorf(yf);
                g_corner[n * 4 + 0] = x0;
                g_corner[n * 4 + 1] = y0;
                g_corner[n * 4 + 2] = xf - x0;
                g_corner[n * 4 + 3] = yf - y0;
            } else if (head == 1) {
                float o[12];
#pragma unroll
                for (int t = 0; t < 12; t++) o[t] = 0.f;
                for (int j = 0; j < DD; j++) {
                    float h = h2[j];
#pragma unroll
                    for (int t = 0; t < 12; t++) o[t] += h * w3l[j * 12 + t];
                }
                float mx = o[0];
#pragma unroll
                for (int t = 1; t < 12; t++) mx = fmaxf(mx, o[t]);
                float s = 0.f;
#pragma unroll
                for (int t = 0; t < 12; t++) { o[t] = expf(o[t] - mx); s += o[t]; }
                float inv = 1.f / s;
                float ent = 0.f;
#pragma unroll
                for (int t = 0; t < 12; t++) {
                    float pr = o[t] * inv;
                    g_sel_layer[n * 12 + t] = pr;
                    ent += logf(pr + 1e-8f) * pr;
                }
                redv = ent;
            } else {
                float o0 = 0.f;
                for (int j = 0; j < DD; j++) o0 += h2[j] * w3c[j];
                float s = 1.f / (1.f + expf(-o0));
                g_sel_scale[n] = s;
                float d = s - 0.5f;
                redv = d * d;
            }
        }
    }
    redv = wred(redv);
    if ((tid & 31) == 0) redbuf[tid >> 5] = redv;
    __syncthreads();
    if (tid == 0) {
        float s = 0.f;
#pragma unroll
        for (int w = 0; w < 8; w++) s += redbuf[w];
        if (head == 1) g_ent_part[blockIdx.x] = s;
        else if (head == 2) g_sq_part[blockIdx.x] = s;
    }
}

// ---------------- K3: feat[l,b,d,hw] = sum_c lt[l,b,c,hw] * cw[l,d,c] ----------------
__global__ void k_conv(const float* __restrict__ lt, const float* __restrict__ cw) {
    extern __shared__ float cws[];  // [16][768]
    int dg = blockIdx.x, b = blockIdx.y, l = blockIdx.z;
    const float* cwp = cw + (size_t)(l * DD + dg * 16) * CC;
    for (int i = threadIdx.x; i < 16 * CC; i += 256) cws[i] = cwp[i];
    __syncthreads();
    int hw = threadIdx.x;
    const float* ltp = lt + (size_t)(l * BB + b) * CC * HWN;
    float acc[16];
#pragma unroll
    for (int k = 0; k < 16; k++) acc[k] = 0.f;
    for (int c = 0; c < CC; c += 4) {
        float v0 = ltp[(c + 0) * HWN + hw];
        float v1 = ltp[(c + 1) * HWN + hw];
        float v2 = ltp[(c + 2) * HWN + hw];
        float v3 = ltp[(c + 3) * HWN + hw];
#pragma unroll
        for (int k = 0; k < 16; k++) {
            float4 w = *(const float4*)&cws[k * CC + c];
            acc[k] += w.x * v0 + w.y * v1 + w.z * v2 + w.w * v3;
        }
    }
    float* fp = g_feat + (size_t)((l * BB + b) * DD + dg * 16) * HWN;
#pragma unroll
    for (int k = 0; k < 16; k++) fp[k * HWN + hw] = acc[k];
}

// ---------------- K4: bilinear sample + ow dot, feat tile in smem ----------------
__global__ void k_samp(const float* __restrict__ ow, int N, int ppb) {
    extern __shared__ float fs[];  // [256][129] transposed feat
    int b = blockIdx.y, l = blockIdx.z;
    const float* fp = g_feat + (size_t)(l * BB + b) * DD * HWN;
    for (int idx = threadIdx.x; idx < DD * HWN; idx += 256) {
        int d = idx >> 8, hw = idx & 255;
        fs[hw * 129 + d] = fp[d * HWN + hw];
    }
    __syncthreads();
    int lane = threadIdx.x & 31, warp = threadIdx.x >> 5;
    int base = blockIdx.x * ppb;
    int end = min(base + ppb, N);
    float* outp = g_part + (size_t)(l * BB + b) * N;
    for (int n = base + warp; n < end; n += 8) {
        float4 cd = *(const float4*)&g_corner[n * 4];
        float wl = g_sel_layer[n * 12 + l];
        int x0 = (int)cd.x, y0 = (int)cd.y;
        float wx1 = cd.z, wy1 = cd.w;
        float wx0 = 1.f - wx1, wy0 = 1.f - wy1;
        float fx0 = (x0 >= 0 && x0 < 16) ? wx0 : 0.f;
        float fx1 = (x0 >= -1 && x0 < 15) ? wx1 : 0.f;
        float fy0 = (y0 >= 0 && y0 < 16) ? wy0 : 0.f;
        float fy1 = (y0 >= -1 && y0 < 15) ? wy1 : 0.f;
        int xc0 = min(max(x0, 0), 15), xc1 = min(max(x0 + 1, 0), 15);
        int yc0 = min(max(y0, 0), 15), yc1 = min(max(y0 + 1, 0), 15);
        float w00 = fx0 * fy0, w10 = fx1 * fy0, w01 = fx0 * fy1, w11 = fx1 * fy1;
        int p00 = (yc0 * 16 + xc0) * 129, p10 = (yc0 * 16 + xc1) * 129;
        int p01 = (yc1 * 16 + xc0) * 129, p11 = (yc1 * 16 + xc1) * 129;
        float acc = 0.f;
#pragma unroll
        for (int m = 0; m < 4; m++) {
            int d = lane + 32 * m;
            float o = ow[n * DD + d];
            float f = w00 * fs[p00 + d] + w10 * fs[p10 + d] +
                      w01 * fs[p01 + d] + w11 * fs[p11 + d];
            acc += f * o;
        }
        acc = wred(acc);
        if (lane == 0) outp[n] = wl * acc;
    }
}

// ---------------- K5: global path + combine + reg ----------------
__global__ void k_final(const float* __restrict__ ow, const float* __restrict__ bias,
                        float* __restrict__ out, int N, int npart, int write_reg) {
    __shared__ float gbs[LL * BB * DD];
    for (int i = threadIdx.x; i < LL * BB * DD; i += blockDim.x) gbs[i] = g_gb[i];
    __syncthreads();
    int lane = threadIdx.x & 31, warp = threadIdx.x >> 5;
    int gw = blockIdx.x * 8 + warp, nw = gridDim.x * 8;
    if (gw == 0 && write_reg) {
        float es = 0.f, ss = 0.f;
        for (int i = lane; i < npart; i += 32) {
            es += g_ent_part[i];
            ss += g_sq_part[i];
        }
        es = wred(es);
        ss = wred(ss);
        if (lane == 0) {
            float reg = (es / (float)N) / 2.4849066497880004f + ss / (float)N;
            out[4 * N] = reg;
        }
    }
    for (int n = gw; n < N; n += nw) {
        float s = g_sel_scale[n];
        float wl[12];
#pragma unroll
        for (int t = 0; t < 12; t++) wl[t] = g_sel_layer[n * 12 + t];
        float o[4];
#pragma unroll
        for (int m = 0; m < 4; m++) o[m] = ow[n * DD + lane + 32 * m];
        float bn = bias[n];
#pragma unroll
        for (int b = 0; b < 4; b++) {
            float a = 0.f;
#pragma unroll
            for (int m = 0; m < 4; m++) {
                int d = lane + 32 * m;
                float vg = 0.f;
#pragma unroll
                for (int t = 0; t < 12; t++) vg += wl[t] * gbs[(t * BB + b) * DD + d];
                a += vg * o[m];
            }
            a = wred(a);
            if (lane == 0) {
                float yl = 0.f;
#pragma unroll
                for (int t = 0; t < 12; t++) yl += g_part[(size_t)(t * BB + b) * N + n];
                out[b * N + n] = ((1.f - s) * yl + s * a) * (1.0f / 128.0f) + bn;
            }
        }
    }
}

// ---------------- launch ----------------
extern "C" void kernel_launch(void* const* d_in, const int* in_sizes, int n_in,
                              void* d_out, int out_size) {
    const float* lt     = (const float*)d_in[0];
    const float* gt     = (const float*)d_in[1];
    const float* coords = (const float*)d_in[2];
    const float* cw     = (const float*)d_in[3];
    const float* gw     = (const float*)d_in[4];
    const float* W1     = (const float*)d_in[5];
    const float* b1     = (const float*)d_in[6];
    const float* W2     = (const float*)d_in[7];
    const float* b2     = (const float*)d_in[8];
    const float* w3s    = (const float*)d_in[9];
    const float* w3l    = (const float*)d_in[10];
    const float* w3c    = (const float*)d_in[11];
    const float* ow     = (const float*)d_in[12];
    const float* bias   = (const float*)d_in[13];
    float* out = (float*)d_out;
    int N = in_sizes[13];

    cudaFuncSetAttribute(k_sel, cudaFuncAttributeMaxDynamicSharedMemorySize, SEL_SMEM_BYTES);
    cudaFuncSetAttribute(k_conv, cudaFuncAttributeMaxDynamicSharedMemorySize, 16 * CC * 4);
    cudaFuncSetAttribute(k_samp, cudaFuncAttributeMaxDynamicSharedMemorySize, 256 * 129 * 4);

    k_gb<<<LL * BB, 128>>>(gt, gw);

    int chunks = (N + 63) / 64;
    k_sel<<<dim3(chunks, 3), 256, SEL_SMEM_BYTES>>>(coords, W1, b1, W2, b2, w3s, w3l, w3c, N);

    k_conv<<<dim3(8, BB, LL), 256, 16 * CC * 4>>>(lt, cw);

    int CH = 50;
    int ppb = (N + CH - 1) / CH;
    k_samp<<<dim3(CH, BB, LL), 256, 256 * 129 * 4>>>(ow, N, ppb);

    k_final<<<148, 256>>>(ow, bias, out, N, chunks, (out_size > 4 * N) ? 1 : 0);
}

// round 3
// speedup vs baseline: 1.7142x; 1.7142x over previous
#include <cuda_runtime.h>

#define LL 12
#define BB 4
#define CC 768
#define HWN 256
#define DD 128
#define NMAX 30000
#define NCELL 289

typedef unsigned long long u64;

// ---------------- device scratch (no allocations allowed) ----------------
__device__ float g_feat[LL * BB * HWN * DD];     // [l][b][hw][d]
__device__ float g_ylocal[BB * NMAX];            // local path, layer-summed
__device__ float g_sel_layer[NMAX * LL];
__device__ float g_sel_scale[NMAX];
__device__ float g_corner[NMAX * 4];             // x0f, y0f, wx, wy
__device__ float g_gb[LL * BB * DD];
__device__ float g_ent_part[2048];
__device__ float g_sq_part[2048];
__device__ int   g_cell[NMAX];
__device__ int   g_cellcnt[NCELL];
__device__ int   g_celloff[NCELL + 1];
__device__ int   g_cellfill[NCELL];
__device__ int   g_order[NMAX];

// ---------------- f32x2 packed-FMA helpers ----------------
__device__ __forceinline__ u64 pk2(float lo, float hi) {
    u64 r; asm("mov.b64 %0, {%1,%2};" : "=l"(r) : "f"(lo), "f"(hi)); return r;
}
__device__ __forceinline__ u64 ffma2(u64 a, u64 b, u64 c) {
    u64 d; asm("fma.rn.f32x2 %0, %1, %2, %3;" : "=l"(d) : "l"(a), "l"(b), "l"(c)); return d;
}
__device__ __forceinline__ float2 up2(u64 v) {
    float2 f; asm("mov.b64 {%0,%1}, %2;" : "=f"(f.x), "=f"(f.y) : "l"(v)); return f;
}

__device__ __forceinline__ float gelu_exact(float x) {
    return 0.5f * x * (1.0f + erff(x * 0.70710678118654752440f));
}
__device__ __forceinline__ float wred(float v) {
#pragma unroll
    for (int o = 16; o; o >>= 1) v += __shfl_xor_sync(0xffffffffu, v, o);
    return v;
}

// ---------------- K0: zero bin counters ----------------
__global__ void k_zero() {
    int t = threadIdx.x;
    if (t < NCELL) { g_cellcnt[t] = 0; g_cellfill[t] = 0; }
}

// ---------------- K1: gb[l,b,d] = sum_c gt[l,b,c] * gw[l,d,c] ----------------
__global__ void k_gb(const float* __restrict__ gt, const float* __restrict__ gw) {
    __shared__ float gts[CC];
    int lb = blockIdx.x;
    for (int i = threadIdx.x; i < CC; i += blockDim.x) gts[i] = gt[lb * CC + i];
    __syncthreads();
    int d = threadIdx.x;
    int l = lb >> 2;
    const float4* w4 = (const float4*)(gw + (size_t)(l * DD + d) * CC);
    const float4* t4 = (const float4*)gts;
    float acc = 0.f;
#pragma unroll 8
    for (int c4 = 0; c4 < CC / 4; c4++) {
        float4 w = w4[c4];
        float4 t = t4[c4];
        acc += w.x * t.x + w.y * t.y + w.z * t.z + w.w * t.w;
    }
    g_gb[lb * DD + d] = acc;
}

// ---------------- K2: selector MLPs (3 heads), 64 points per block ----------------
#define SEL_W_F   (192 * DD)
#define SEL_PE_F  (64 * 192)
#define SEL_H_F   (64 * 132)
#define SEL_SMEM_BYTES ((SEL_W_F + SEL_PE_F + SEL_H_F) * 4)

__global__ void k_sel(const float* __restrict__ coords,
                      const float* __restrict__ W1, const float* __restrict__ b1,
                      const float* __restrict__ W2, const float* __restrict__ b2,
                      const float* __restrict__ w3s, const float* __restrict__ w3l,
                      const float* __restrict__ w3c, int N) {
    extern __shared__ float sm[];
    float* Ws   = sm;                       // W1 then W2
    float* peh2 = sm + SEL_W_F;             // pe [64][192], later h2 [64][132]
    float* h1   = sm + SEL_W_F + SEL_PE_F;  // [64][132]
    __shared__ float redbuf[8];

    const int head = blockIdx.y;
    const int base = blockIdx.x * 64;
    const int tid = threadIdx.x;

    const float* W1p = W1 + head * 192 * DD;
    for (int i = tid; i < 192 * DD; i += 256) Ws[i] = W1p[i];
    for (int idx = tid; idx < 64 * 192; idx += 256) {
        int p = idx / 192, i = idx - p * 192;
        int n = base + p;
        float v = 0.f;
        if (n < N) {
            int c = i >> 6;
            int t = i & 63;
            int k = t & 31;
            float f = 3.14159265358979323846f * exp2f((float)k * (8.0f / 31.0f));
            float ang = coords[n * 3 + c] * f;
            v = (t < 32) ? sinf(ang) : cosf(ang);
        }
        peh2[idx] = v;
    }
    __syncthreads();

    const int tx = tid & 31, ty = tid >> 5;
    const int j0 = tx * 4, p0 = ty * 8;

    u64 acc0[8], acc1[8];
#pragma unroll
    for (int p = 0; p < 8; p++) { acc0[p] = 0ULL; acc1[p] = 0ULL; }

    // GEMM1: [64 x 192] @ [192 x 128] with packed f32x2 FMA
    for (int i = 0; i < 192; i++) {
        const double* wd = (const double*)&Ws[i * DD + j0];
        u64 w01 = __double_as_longlong(wd[0]);
        u64 w23 = __double_as_longlong(wd[1]);
#pragma unroll
        for (int p = 0; p < 8; p++) {
            float pv = peh2[(p0 + p) * 192 + i];
            u64 pv2 = pk2(pv, pv);
            acc0[p] = ffma2(pv2, w01, acc0[p]);
            acc1[p] = ffma2(pv2, w23, acc1[p]);
        }
    }
    {
        float4 bv = *(const float4*)&b1[head * DD + j0];
#pragma unroll
        for (int p = 0; p < 8; p++) {
            float2 a01 = up2(acc0[p]);
            float2 a23 = up2(acc1[p]);
            float4 h;
            h.x = gelu_exact(a01.x + bv.x);
            h.y = gelu_exact(a01.y + bv.y);
            h.z = gelu_exact(a23.x + bv.z);
            h.w = gelu_exact(a23.y + bv.w);
            *(float4*)&h1[(p0 + p) * 132 + j0] = h;
        }
    }
    __syncthreads();
    const float* W2p = W2 + head * DD * DD;
    for (int i = tid; i < DD * DD; i += 256) Ws[i] = W2p[i];
    __syncthreads();

#pragma unroll
    for (int p = 0; p < 8; p++) { acc0[p] = 0ULL; acc1[p] = 0ULL; }
    // GEMM2: [64 x 128] @ [128 x 128]
    for (int i = 0; i < DD; i++) {
        const double* wd = (const double*)&Ws[i * DD + j0];
        u64 w01 = __double_as_longlong(wd[0]);
        u64 w23 = __double_as_longlong(wd[1]);
#pragma unroll
        for (int p = 0; p < 8; p++) {
            float pv = h1[(p0 + p) * 132 + i];
            u64 pv2 = pk2(pv, pv);
            acc0[p] = ffma2(pv2, w01, acc0[p]);
            acc1[p] = ffma2(pv2, w23, acc1[p]);
        }
    }
    {
        float4 bv = *(const float4*)&b2[head * DD + j0];
#pragma unroll
        for (int p = 0; p < 8; p++) {
            float2 a01 = up2(acc0[p]);
            float2 a23 = up2(acc1[p]);
            float4 h;
            h.x = gelu_exact(a01.x + bv.x);
            h.y = gelu_exact(a01.y + bv.y);
            h.z = gelu_exact(a23.x + bv.z);
            h.w = gelu_exact(a23.y + bv.w);
            *(float4*)&peh2[(p0 + p) * 132 + j0] = h;  // h2 tile
        }
    }
    __syncthreads();

    // phase3: one thread per point (threads 0..63)
    float redv = 0.f;
    if (tid < 64) {
        int n = base + tid;
        if (n < N) {
            const float* h2 = &peh2[tid * 132];
            if (head == 0) {
                float o0 = 0.f, o1 = 0.f;
                for (int j = 0; j < DD; j++) {
                    float h = h2[j];
                    o0 += h * w3s[j * 2 + 0];
                    o1 += h * w3s[j * 2 + 1];
                }
                float sx = tanhf(o0), sy = tanhf(o1);
                float xf = (sx + 1.f) * 8.f - 0.5f;
                float yf = (sy + 1.f) * 8.f - 0.5f;
                float x0 = floorf(xf), y0 = floorf(yf);
                g_corner[n * 4 + 0] = x0;
                g_corner[n * 4 + 1] = y0;
                g_corner[n * 4 + 2] = xf - x0;
                g_corner[n * 4 + 3] = yf - y0;
                int cell = ((int)y0 + 1) * 17 + ((int)x0 + 1);
                g_cell[n] = cell;
                atomicAdd(&g_cellcnt[cell], 1);
            } else if (head == 1) {
                float o[12];
#pragma unroll
                for (int t = 0; t < 12; t++) o[t] = 0.f;
                for (int j = 0; j < DD; j++) {
                    float h = h2[j];
#pragma unroll
                    for (int t = 0; t < 12; t++) o[t] += h * w3l[j * 12 + t];
                }
                float mx = o[0];
#pragma unroll
                for (int t = 1; t < 12; t++) mx = fmaxf(mx, o[t]);
                float s = 0.f;
#pragma unroll
                for (int t = 0; t < 12; t++) { o[t] = expf(o[t] - mx); s += o[t]; }
                float inv = 1.f / s;
                float ent = 0.f;
#pragma unroll
                for (int t = 0; t < 12; t++) {
                    float pr = o[t] * inv;
                    g_sel_layer[n * 12 + t] = pr;
                    ent += logf(pr + 1e-8f) * pr;
                }
                redv = ent;
            } else {
                float o0 = 0.f;
                for (int j = 0; j < DD; j++) o0 += h2[j] * w3c[j];
                float s = 1.f / (1.f + expf(-o0));
                g_sel_scale[n] = s;
                float d = s - 0.5f;
                redv = d * d;
            }
        }
    }
    redv = wred(redv);
    if ((tid & 31) == 0) redbuf[tid >> 5] = redv;
    __syncthreads();
    if (tid == 0) {
        float s = 0.f;
#pragma unroll
        for (int w = 0; w < 8; w++) s += redbuf[w];
        if (head == 1) g_ent_part[blockIdx.x] = s;
        else if (head == 2) g_sq_part[blockIdx.x] = s;
    }
}

// ---------------- K2b: prefix sum over cell histogram ----------------
__global__ void k_scan() {
    __shared__ int s[NCELL];
    int t = threadIdx.x;
    if (t < NCELL) s[t] = g_cellcnt[t];
    __syncthreads();
    if (t == 0) {
        int acc = 0;
        for (int i = 0; i < NCELL; i++) { g_celloff[i] = acc; acc += s[i]; }
        g_celloff[NCELL] = acc;
    }
}

// ---------------- K2c: scatter points into cell-sorted order ----------------
__global__ void k_scatter(int N) {
    int n = blockIdx.x * 256 + threadIdx.x;
    if (n < N) {
        int c = g_cell[n];
        int pos = atomicAdd(&g_cellfill[c], 1);
        g_order[g_celloff[c] + pos] = n;
    }
}

// ---------------- K3: feat[l,b,hw,d] = sum_c lt[l,b,c,hw] * cw[l,d,c] ----------------
__global__ void k_conv(const float* __restrict__ lt, const float* __restrict__ cw) {
    extern __shared__ float cws[];  // [16][768]
    int dg = blockIdx.x, b = blockIdx.y, l = blockIdx.z;
    const float* cwp = cw + (size_t)(l * DD + dg * 16) * CC;
    for (int i = threadIdx.x; i < 16 * CC; i += 256) cws[i] = cwp[i];
    __syncthreads();
    int hw = threadIdx.x;
    const float* ltp = lt + (size_t)(l * BB + b) * CC * HWN;
    float acc[16];
#pragma unroll
    for (int k = 0; k < 16; k++) acc[k] = 0.f;
    for (int c = 0; c < CC; c += 4) {
        float v0 = ltp[(c + 0) * HWN + hw];
        float v1 = ltp[(c + 1) * HWN + hw];
        float v2 = ltp[(c + 2) * HWN + hw];
        float v3 = ltp[(c + 3) * HWN + hw];
#pragma unroll
        for (int k = 0; k < 16; k++) {
            float4 w = *(const float4*)&cws[k * CC + c];
            acc[k] += w.x * v0 + w.y * v1 + w.z * v2 + w.w * v3;
        }
    }
    float* fp = g_feat + ((size_t)(l * BB + b) * HWN + hw) * DD + dg * 16;
#pragma unroll
    for (int k4 = 0; k4 < 4; k4++)
        *(float4*)&fp[k4 * 4] = make_float4(acc[k4 * 4], acc[k4 * 4 + 1],
                                            acc[k4 * 4 + 2], acc[k4 * 4 + 3]);
}

// ---------------- K4: bilinear sample + ow dot, cell-ordered, L1-resident feat ----------------
__global__ void k_samp2(const float* __restrict__ ow, int N) {
    int lane = threadIdx.x & 31, warp = threadIdx.x >> 5;
    int base = blockIdx.x * 64 + warp * 8;
    for (int j = 0; j < 8; j++) {
        int idx = base + j;
        if (idx >= N) break;
        int n = g_order[idx];
        float4 cd = *(const float4*)&g_corner[n * 4];
        int x0 = (int)cd.x, y0 = (int)cd.y;
        float wx1 = cd.z, wy1 = cd.w, wx0 = 1.f - wx1, wy0 = 1.f - wy1;
        float fx0 = (x0 >= 0) ? wx0 : 0.f;
        float fx1 = (x0 < 15) ? wx1 : 0.f;
        float fy0 = (y0 >= 0) ? wy0 : 0.f;
        float fy1 = (y0 < 15) ? wy1 : 0.f;
        int xc0 = max(x0, 0), xc1 = min(x0 + 1, 15);
        int yc0 = max(y0, 0), yc1 = min(y0 + 1, 15);
        float c00 = fx0 * fy0, c10 = fx1 * fy0, c01 = fx0 * fy1, c11 = fx1 * fy1;
        u64 W00 = pk2(c00, c00), W10 = pk2(c10, c10);
        u64 W01 = pk2(c01, c01), W11 = pk2(c11, c11);
        int p00 = (yc0 * 16 + xc0) << 7, p10 = (yc0 * 16 + xc1) << 7;
        int p01 = (yc1 * 16 + xc0) << 7, p11 = (yc1 * 16 + xc1) << 7;
        float4 o4 = *(const float4*)&ow[n * DD + (lane << 2)];
        u64 oa = pk2(o4.x, o4.y), ob = pk2(o4.z, o4.w);
        u64 acc[4];
#pragma unroll
        for (int b = 0; b < 4; b++) acc[b] = 0ULL;
#pragma unroll
        for (int l = 0; l < 12; l++) {
            float wlv = g_sel_layer[n * 12 + l];
            u64 wl2 = pk2(wlv, wlv);
#pragma unroll
            for (int b = 0; b < 4; b++) {
                const float* f = g_feat + (((size_t)(l * 4 + b)) << 15) + (lane << 2);
                ulonglong2 f00 = *(const ulonglong2*)(f + p00);
                ulonglong2 f10 = *(const ulonglong2*)(f + p10);
                ulonglong2 f01 = *(const ulonglong2*)(f + p01);
                ulonglong2 f11 = *(const ulonglong2*)(f + p11);
                u64 va = ffma2(W00, f00.x,
                         ffma2(W10, f10.x,
                         ffma2(W01, f01.x,
                         ffma2(W11, f11.x, 0ULL))));
                u64 vb = ffma2(W00, f00.y,
                         ffma2(W10, f10.y,
                         ffma2(W01, f01.y,
                         ffma2(W11, f11.y, 0ULL))));
                u64 t = ffma2(va, oa, ffma2(vb, ob, 0ULL));
                acc[b] = ffma2(wl2, t, acc[b]);
            }
        }
#pragma unroll
        for (int b = 0; b < 4; b++) {
            float2 r = up2(acc[b]);
            float s = r.x + r.y;
            s = wred(s);
            if (lane == 0) g_ylocal[b * N + n] = s;
        }
    }
}

// ---------------- K5: global path + combine + reg ----------------
__global__ void k_final(const float* __restrict__ ow, const float* __restrict__ bias,
                        float* __restrict__ out, int N, int npart, int write_reg) {
    __shared__ float gbs[LL * BB * DD];
    for (int i = threadIdx.x; i < LL * BB * DD; i += blockDim.x) gbs[i] = g_gb[i];
    __syncthreads();
    int lane = threadIdx.x & 31, warp = threadIdx.x >> 5;
    int gw = blockIdx.x * 8 + warp, nw = gridDim.x * 8;
    if (gw == 0 && write_reg) {
        float es = 0.f, ss = 0.f;
        for (int i = lane; i < npart; i += 32) {
            es += g_ent_part[i];
            ss += g_sq_part[i];
        }
        es = wred(es);
        ss = wred(ss);
        if (lane == 0) {
            float reg = (es / (float)N) / 2.4849066497880004f + ss / (float)N;
            out[4 * N] = reg;
        }
    }
    for (int n = gw; n < N; n += nw) {
        float s = g_sel_scale[n];
        float wl[12];
#pragma unroll
        for (int t = 0; t < 12; t++) wl[t] = g_sel_layer[n * 12 + t];
        float o[4];
#pragma unroll
        for (int m = 0; m < 4; m++) o[m] = ow[n * DD + lane + 32 * m];
        float bn = bias[n];
#pragma unroll
        for (int b = 0; b < 4; b++) {
            float a = 0.f;
#pragma unroll
            for (int m = 0; m < 4; m++) {
                int d = lane + 32 * m;
                float vg = 0.f;
#pragma unroll
                for (int t = 0; t < 12; t++) vg += wl[t] * gbs[(t * BB + b) * DD + d];
                a += vg * o[m];
            }
            a = wred(a);
            if (lane == 0) {
                float yl = g_ylocal[b * N + n];
                out[b * N + n] = ((1.f - s) * yl + s * a) * (1.0f / 128.0f) + bn;
            }
        }
    }
}

// ---------------- launch ----------------
extern "C" void kernel_launch(void* const* d_in, const int* in_sizes, int n_in,
                              void* d_out, int out_size) {
    const float* lt     = (const float*)d_in[0];
    const float* gt     = (const float*)d_in[1];
    const float* coords = (const float*)d_in[2];
    const float* cw     = (const float*)d_in[3];
    const float* gw     = (const float*)d_in[4];
    const float* W1     = (const float*)d_in[5];
    const float* b1     = (const float*)d_in[6];
    const float* W2     = (const float*)d_in[7];
    const float* b2     = (const float*)d_in[8];
    const float* w3s    = (const float*)d_in[9];
    const float* w3l    = (const float*)d_in[10];
    const float* w3c    = (const float*)d_in[11];
    const float* ow     = (const float*)d_in[12];
    const float* bias   = (const float*)d_in[13];
    float* out = (float*)d_out;
    int N = in_sizes[13];

    cudaFuncSetAttribute(k_sel, cudaFuncAttributeMaxDynamicSharedMemorySize, SEL_SMEM_BYTES);
    cudaFuncSetAttribute(k_conv, cudaFuncAttributeMaxDynamicSharedMemorySize, 16 * CC * 4);

    k_zero<<<1, 320>>>();
    k_gb<<<LL * BB, 128>>>(gt, gw);

    int chunks = (N + 63) / 64;
    k_sel<<<dim3(chunks, 3), 256, SEL_SMEM_BYTES>>>(coords, W1, b1, W2, b2, w3s, w3l, w3c, N);

    k_scan<<<1, 512>>>();
    k_scatter<<<(N + 255) / 256, 256>>>(N);

    k_conv<<<dim3(8, BB, LL), 256, 16 * CC * 4>>>(lt, cw);

    k_samp2<<<chunks, 256>>>(ow, N);

    k_final<<<148, 256>>>(ow, bias, out, N, chunks, (out_size > 4 * N) ? 1 : 0);
}

// round 6
// speedup vs baseline: 1.8911x; 1.1032x over previous
#include <cuda_runtime.h>

#define LL 12
#define BB 4
#define CC 768
#define HWN 256
#define DD 128
#define NMAX 30000
#define NCELL 289

typedef unsigned long long u64;

// ---------------- device scratch (no allocations allowed) ----------------
__device__ float g_feat[LL * BB * HWN * DD];     // [l][b][hw][d]
__device__ float g_sel_layer[NMAX * LL];
__device__ float g_sel_scale[NMAX];
__device__ float g_corner[NMAX * 4];             // x0f, y0f, wx, wy
__device__ float g_gb[LL * BB * DD];
__device__ float g_ent_part[2048];
__device__ float g_sq_part[2048];
__device__ int   g_cell[NMAX];
__device__ int   g_cellcnt[NCELL];
__device__ int   g_celloff[NCELL + 1];
__device__ int   g_cellfill[NCELL];
__device__ int   g_order[NMAX];

// ---------------- f32x2 packed helpers ----------------
__device__ __forceinline__ u64 pk2(float lo, float hi) {
    u64 r; asm("mov.b64 %0, {%1,%2};" : "=l"(r) : "f"(lo), "f"(hi)); return r;
}
__device__ __forceinline__ u64 ffma2(u64 a, u64 b, u64 c) {
    u64 d; asm("fma.rn.f32x2 %0, %1, %2, %3;" : "=l"(d) : "l"(a), "l"(b), "l"(c)); return d;
}
__device__ __forceinline__ u64 add2(u64 a, u64 b) {
    u64 d; asm("add.rn.f32x2 %0, %1, %2;" : "=l"(d) : "l"(a), "l"(b)); return d;
}
__device__ __forceinline__ float2 up2(u64 v) {
    float2 f; asm("mov.b64 {%0,%1}, %2;" : "=f"(f.x), "=f"(f.y) : "l"(v)); return f;
}
__device__ __forceinline__ float gelu_exact(float x) {
    return 0.5f * x * (1.0f + erff(x * 0.70710678118654752440f));
}
__device__ __forceinline__ float wred(float v) {
#pragma unroll
    for (int o = 16; o; o >>= 1) v += __shfl_xor_sync(0xffffffffu, v, o);
    return v;
}
__device__ __forceinline__ u64 wred2(u64 v) {
#pragma unroll
    for (int o = 16; o; o >>= 1) v = add2(v, __shfl_xor_sync(0xffffffffu, v, o));
    return v;
}

// ---------------- K0: zero bin counters ----------------
__global__ void k_zero() {
    int t = threadIdx.x;
    if (t < NCELL) { g_cellcnt[t] = 0; g_cellfill[t] = 0; }
}

// ---------------- K1: gb[l,b,d] = sum_c gt[l,b,c] * gw[l,d,c] ----------------
__global__ void k_gb(const float* __restrict__ gt, const float* __restrict__ gw) {
    __shared__ float gts[CC];
    int lb = blockIdx.x;
    for (int i = threadIdx.x; i < CC; i += blockDim.x) gts[i] = gt[lb * CC + i];
    __syncthreads();
    int d = threadIdx.x;
    int l = lb >> 2;
    const float4* w4 = (const float4*)(gw + (size_t)(l * DD + d) * CC);
    const float4* t4 = (const float4*)gts;
    float acc = 0.f;
#pragma unroll 8
    for (int c4 = 0; c4 < CC / 4; c4++) {
        float4 w = w4[c4];
        float4 t = t4[c4];
        acc += w.x * t.x + w.y * t.y + w.z * t.z + w.w * t.w;
    }
    g_gb[lb * DD + d] = acc;
}

// ---------------- K2: selector MLPs (3 heads), 64 points per block ----------------
#define SEL_W_F   (192 * DD)
#define SEL_PE_F  (64 * 192)
#define SEL_H_F   (64 * 132)
#define SEL_SMEM_BYTES ((SEL_W_F + SEL_PE_F + SEL_H_F) * 4)

__global__ void k_sel(const float* __restrict__ coords,
                      const float* __restrict__ W1, const float* __restrict__ b1,
                      const float* __restrict__ W2, const float* __restrict__ b2,
                      const float* __restrict__ w3s, const float* __restrict__ w3l,
                      const float* __restrict__ w3c, int N) {
    extern __shared__ float sm[];
    float* Ws   = sm;                       // W1 then W2
    float* peh2 = sm + SEL_W_F;             // pe [64][192], later h2 [64][132]
    float* h1   = sm + SEL_W_F + SEL_PE_F;  // [64][132]
    __shared__ float redbuf[8];

    const int head = blockIdx.y;
    const int base = blockIdx.x * 64;
    const int tid = threadIdx.x;

    const float* W1p = W1 + head * 192 * DD;
    for (int i = tid; i < 192 * DD; i += 256) Ws[i] = W1p[i];
    for (int idx = tid; idx < 64 * 192; idx += 256) {
        int p = idx / 192, i = idx - p * 192;
        int n = base + p;
        float v = 0.f;
        if (n < N) {
            int c = i >> 6;
            int t = i & 63;
            int k = t & 31;
            float f = 3.14159265358979323846f * exp2f((float)k * (8.0f / 31.0f));
            float ang = coords[n * 3 + c] * f;
            v = (t < 32) ? sinf(ang) : cosf(ang);
        }
        peh2[idx] = v;
    }
    __syncthreads();

    const int tx = tid & 31, ty = tid >> 5;
    const int j0 = tx * 4, p0 = ty * 8;

    u64 acc0[8], acc1[8];
#pragma unroll
    for (int p = 0; p < 8; p++) { acc0[p] = 0ULL; acc1[p] = 0ULL; }

    // GEMM1: [64 x 192] @ [192 x 128], float4-vectorized over i
    for (int i = 0; i < 192; i += 4) {
        float4 pr[8];
#pragma unroll
        for (int p = 0; p < 8; p++)
            pr[p] = *(const float4*)&peh2[(p0 + p) * 192 + i];
#pragma unroll
        for (int ii = 0; ii < 4; ii++) {
            float4 w = *(const float4*)&Ws[(i + ii) * DD + j0];
            u64 w01 = pk2(w.x, w.y), w23 = pk2(w.z, w.w);
#pragma unroll
            for (int p = 0; p < 8; p++) {
                float pv = (ii == 0) ? pr[p].x : (ii == 1) ? pr[p].y : (ii == 2) ? pr[p].z : pr[p].w;
                u64 pv2 = pk2(pv, pv);
                acc0[p] = ffma2(pv2, w01, acc0[p]);
                acc1[p] = ffma2(pv2, w23, acc1[p]);
            }
        }
    }
    {
        float4 bv = *(const float4*)&b1[head * DD + j0];
#pragma unroll
        for (int p = 0; p < 8; p++) {
            float2 a01 = up2(acc0[p]);
            float2 a23 = up2(acc1[p]);
            float4 h;
            h.x = gelu_exact(a01.x + bv.x);
            h.y = gelu_exact(a01.y + bv.y);
            h.z = gelu_exact(a23.x + bv.z);
            h.w = gelu_exact(a23.y + bv.w);
            *(float4*)&h1[(p0 + p) * 132 + j0] = h;
        }
    }
    __syncthreads();
    const float* W2p = W2 + head * DD * DD;
    for (int i = tid; i < DD * DD; i += 256) Ws[i] = W2p[i];
    __syncthreads();

#pragma unroll
    for (int p = 0; p < 8; p++) { acc0[p] = 0ULL; acc1[p] = 0ULL; }
    // GEMM2: [64 x 128] @ [128 x 128]
    for (int i = 0; i < DD; i += 4) {
        float4 pr[8];
#pragma unroll
        for (int p = 0; p < 8; p++)
            pr[p] = *(const float4*)&h1[(p0 + p) * 132 + i];
#pragma unroll
        for (int ii = 0; ii < 4; ii++) {
            float4 w = *(const float4*)&Ws[(i + ii) * DD + j0];
            u64 w01 = pk2(w.x, w.y), w23 = pk2(w.z, w.w);
#pragma unroll
            for (int p = 0; p < 8; p++) {
                float pv = (ii == 0) ? pr[p].x : (ii == 1) ? pr[p].y : (ii == 2) ? pr[p].z : pr[p].w;
                u64 pv2 = pk2(pv, pv);
                acc0[p] = ffma2(pv2, w01, acc0[p]);
                acc1[p] = ffma2(pv2, w23, acc1[p]);
            }
        }
    }
    {
        float4 bv = *(const float4*)&b2[head * DD + j0];
#pragma unroll
        for (int p = 0; p < 8; p++) {
            float2 a01 = up2(acc0[p]);
            float2 a23 = up2(acc1[p]);
            float4 h;
            h.x = gelu_exact(a01.x + bv.x);
            h.y = gelu_exact(a01.y + bv.y);
            h.z = gelu_exact(a23.x + bv.z);
            h.w = gelu_exact(a23.y + bv.w);
            *(float4*)&peh2[(p0 + p) * 132 + j0] = h;  // h2 tile
        }
    }
    __syncthreads();

    // phase3: one thread per point
    float redv = 0.f;
    if (tid < 64) {
        int n = base + tid;
        if (n < N) {
            const float* h2 = &peh2[tid * 132];
            if (head == 0) {
                float o0 = 0.f, o1 = 0.f;
                for (int j = 0; j < DD; j++) {
                    float h = h2[j];
                    o0 += h * w3s[j * 2 + 0];
                    o1 += h * w3s[j * 2 + 1];
                }
                float sx = tanhf(o0), sy = tanhf(o1);
                float xf = (sx + 1.f) * 8.f - 0.5f;
                float yf = (sy + 1.f) * 8.f - 0.5f;
                float x0 = floorf(xf), y0 = floorf(yf);
                g_corner[n * 4 + 0] = x0;
                g_corner[n * 4 + 1] = y0;
                g_corner[n * 4 + 2] = xf - x0;
                g_corner[n * 4 + 3] = yf - y0;
                int cell = ((int)y0 + 1) * 17 + ((int)x0 + 1);
                g_cell[n] = cell;
                atomicAdd(&g_cellcnt[cell], 1);
            } else if (head == 1) {
                float o[12];
#pragma unroll
                for (int t = 0; t < 12; t++) o[t] = 0.f;
                for (int j = 0; j < DD; j++) {
                    float h = h2[j];
#pragma unroll
                    for (int t = 0; t < 12; t++) o[t] += h * w3l[j * 12 + t];
                }
                float mx = o[0];
#pragma unroll
                for (int t = 1; t < 12; t++) mx = fmaxf(mx, o[t]);
                float s = 0.f;
#pragma unroll
                for (int t = 0; t < 12; t++) { o[t] = expf(o[t] - mx); s += o[t]; }
                float inv = 1.f / s;
                float ent = 0.f;
#pragma unroll
                for (int t = 0; t < 12; t++) {
                    float pr = o[t] * inv;
                    g_sel_layer[n * 12 + t] = pr;
                    ent += logf(pr + 1e-8f) * pr;
                }
                redv = ent;
            } else {
                float o0 = 0.f;
                for (int j = 0; j < DD; j++) o0 += h2[j] * w3c[j];
                float s = 1.f / (1.f + expf(-o0));
                g_sel_scale[n] = s;
                float d = s - 0.5f;
                redv = d * d;
            }
        }
    }
    redv = wred(redv);
    if ((tid & 31) == 0) redbuf[tid >> 5] = redv;
    __syncthreads();
    if (tid == 0) {
        float s = 0.f;
#pragma unroll
        for (int w = 0; w < 8; w++) s += redbuf[w];
        if (head == 1) g_ent_part[blockIdx.x] = s;
        else if (head == 2) g_sq_part[blockIdx.x] = s;
    }
}

// ---------------- K2b: prefix sum over cell histogram ----------------
__global__ void k_scan() {
    __shared__ int s[NCELL];
    int t = threadIdx.x;
    if (t < NCELL) s[t] = g_cellcnt[t];
    __syncthreads();
    if (t == 0) {
        int acc = 0;
        for (int i = 0; i < NCELL; i++) { g_celloff[i] = acc; acc += s[i]; }
        g_celloff[NCELL] = acc;
    }
}

// ---------------- K2c: scatter points into cell-sorted order ----------------
__global__ void k_scatter(int N) {
    int n = blockIdx.x * 256 + threadIdx.x;
    if (n < N) {
        int c = g_cell[n];
        int pos = atomicAdd(&g_cellfill[c], 1);
        g_order[g_celloff[c] + pos] = n;
    }
}

// ---------------- K3: feat[l,b,hw,d] = sum_c lt[l,b,c,hw] * cw[l,d,c] ----------------
// weights staged TRANSPOSED in smem: cws_T[c][k] with pad 18 -> FFMA2 on k-pairs
__global__ void k_conv(const float* __restrict__ lt, const float* __restrict__ cw) {
    extern __shared__ float cws[];  // [768][18]
    int dg = blockIdx.x, b = blockIdx.y, l = blockIdx.z;
    const float* cwp = cw + (size_t)(l * DD + dg * 16) * CC;
    for (int i = threadIdx.x; i < 16 * CC; i += 256) {
        int k = i / CC, c = i - k * CC;
        cws[c * 18 + k] = cwp[i];
    }
    __syncthreads();
    int hw = threadIdx.x;
    const float* ltp = lt + (size_t)(l * BB + b) * CC * HWN;
    u64 acc[8];
#pragma unroll
    for (int k2 = 0; k2 < 8; k2++) acc[k2] = 0ULL;
    for (int c = 0; c < CC; c += 4) {
        float v0 = ltp[(c + 0) * HWN + hw];
        float v1 = ltp[(c + 1) * HWN + hw];
        float v2 = ltp[(c + 2) * HWN + hw];
        float v3 = ltp[(c + 3) * HWN + hw];
#pragma unroll
        for (int cc = 0; cc < 4; cc++) {
            float v = (cc == 0) ? v0 : (cc == 1) ? v1 : (cc == 2) ? v2 : v3;
            u64 v2p = pk2(v, v);
            const u64* wrow = (const u64*)&cws[(c + cc) * 18];
#pragma unroll
            for (int k2 = 0; k2 < 8; k2++)
                acc[k2] = ffma2(v2p, wrow[k2], acc[k2]);
        }
    }
    float* fp = g_feat + ((size_t)(l * BB + b) * HWN + hw) * DD + dg * 16;
#pragma unroll
    for (int k2 = 0; k2 < 8; k2++) ((u64*)fp)[k2] = acc[k2];
}

// ---------------- K4: fused bilinear sample + global path + combine ----------------
__global__ void __launch_bounds__(256) k_sampf(const float* __restrict__ ow,
                                               const float* __restrict__ bias,
                                               float* __restrict__ out,
                                               int N, int npart, int write_reg) {
    __shared__ float gbs[LL * BB * DD];
    for (int i = threadIdx.x; i < LL * BB * DD; i += 256) gbs[i] = g_gb[i];
    __syncthreads();
    int lane = threadIdx.x & 31, warp = threadIdx.x >> 5;

    if (blockIdx.x == 0 && warp == 0 && write_reg) {
        float es = 0.f, ss = 0.f;
        for (int i = lane; i < npart; i += 32) {
            es += g_ent_part[i];
            ss += g_sq_part[i];
        }
        es = wred(es);
        ss = wred(ss);
        if (lane == 0) {
            float reg = (es / (float)N) / 2.4849066497880004f + ss / (float)N;
            out[4 * N] = reg;
        }
    }

    int base = blockIdx.x * 64 + warp * 8;
    for (int j = 0; j < 8; j++) {
        int idx = base + j;
        if (idx >= N) break;
        int n = g_order[idx];
        float4 cd = *(const float4*)&g_corner[n * 4];
        int x0 = (int)cd.x, y0 = (int)cd.y;
        float wx1 = cd.z, wy1 = cd.w, wx0 = 1.f - wx1, wy0 = 1.f - wy1;
        float fx0 = (x0 >= 0) ? wx0 : 0.f;
        float fx1 = (x0 < 15) ? wx1 : 0.f;
        float fy0 = (y0 >= 0) ? wy0 : 0.f;
        float fy1 = (y0 < 15) ? wy1 : 0.f;
        int xc0 = max(x0, 0), xc1 = min(x0 + 1, 15);
        int yc0 = max(y0, 0), yc1 = min(y0 + 1, 15);
        float c00 = fx0 * fy0, c10 = fx1 * fy0, c01 = fx0 * fy1, c11 = fx1 * fy1;
        u64 W00 = pk2(c00, c00), W10 = pk2(c10, c10);
        u64 W01 = pk2(c01, c01), W11 = pk2(c11, c11);
        int p00 = (yc0 * 16 + xc0) << 7, p10 = (yc0 * 16 + xc1) << 7;
        int p01 = (yc1 * 16 + xc0) << 7, p11 = (yc1 * 16 + xc1) << 7;

        float4 o4 = *(const float4*)&ow[n * DD + (lane << 2)];
        u64 oa = pk2(o4.x, o4.y), ob = pk2(o4.z, o4.w);

        float4 wlv0 = *(const float4*)&g_sel_layer[n * 12];
        float4 wlv1 = *(const float4*)&g_sel_layer[n * 12 + 4];
        float4 wlv2 = *(const float4*)&g_sel_layer[n * 12 + 8];
        float wl[12] = {wlv0.x, wlv0.y, wlv0.z, wlv0.w,
                        wlv1.x, wlv1.y, wlv1.z, wlv1.w,
                        wlv2.x, wlv2.y, wlv2.z, wlv2.w};

        u64 accL[4], vga[4], vgb[4];
#pragma unroll
        for (int b = 0; b < 4; b++) { accL[b] = 0ULL; vga[b] = 0ULL; vgb[b] = 0ULL; }

#pragma unroll
        for (int l = 0; l < 12; l++) {
            u64 wl2 = pk2(wl[l], wl[l]);
#pragma unroll
            for (int b = 0; b < 4; b++) {
                const float* f = g_feat + (((size_t)(l * 4 + b)) << 15) + (lane << 2);
                ulonglong2 f00 = *(const ulonglong2*)(f + p00);
                ulonglong2 f10 = *(const ulonglong2*)(f + p10);
                ulonglong2 f01 = *(const ulonglong2*)(f + p01);
                ulonglong2 f11 = *(const ulonglong2*)(f + p11);
                u64 va = ffma2(W00, f00.x,
                         ffma2(W10, f10.x,
                         ffma2(W01, f01.x,
                         ffma2(W11, f11.x, 0ULL))));
                u64 vb = ffma2(W00, f00.y,
                         ffma2(W10, f10.y,
                         ffma2(W01, f01.y,
                         ffma2(W11, f11.y, 0ULL))));
                u64 t = ffma2(va, oa, ffma2(vb, ob, 0ULL));
                accL[b] = ffma2(wl2, t, accL[b]);

                const ulonglong2* gg = (const ulonglong2*)&gbs[(l * 4 + b) * DD + (lane << 2)];
                ulonglong2 g2 = *gg;
                vga[b] = ffma2(wl2, g2.x, vga[b]);
                vgb[b] = ffma2(wl2, g2.y, vgb[b]);
            }
        }

        float s = g_sel_scale[n];
        float bn = bias[n];
        u64 s2 = pk2(s, s), s1m = pk2(1.f - s, 1.f - s);
        float val[4];
#pragma unroll
        for (int b = 0; b < 4; b++) {
            u64 glob = ffma2(vga[b], oa, ffma2(vgb[b], ob, 0ULL));
            u64 comb = ffma2(s1m, accL[b], ffma2(s2, glob, 0ULL));
            float2 r = up2(comb);
            val[b] = r.x + r.y;
        }
        u64 v01 = wred2(pk2(val[0], val[1]));
        u64 v23 = wred2(pk2(val[2], val[3]));
        if (lane == 0) {
            float2 a = up2(v01), c = up2(v23);
            out[0 * N + n] = a.x * (1.0f / 128.0f) + bn;
            out[1 * N + n] = a.y * (1.0f / 128.0f) + bn;
            out[2 * N + n] = c.x * (1.0f / 128.0f) + bn;
            out[3 * N + n] = c.y * (1.0f / 128.0f) + bn;
        }
    }
}

// ---------------- launch ----------------
extern "C" void kernel_launch(void* const* d_in, const int* in_sizes, int n_in,
                              void* d_out, int out_size) {
    const float* lt     = (const float*)d_in[0];
    const float* gt     = (const float*)d_in[1];
    const float* coords = (const float*)d_in[2];
    const float* cw     = (const float*)d_in[3];
    const float* gw     = (const float*)d_in[4];
    const float* W1     = (const float*)d_in[5];
    const float* b1     = (const float*)d_in[6];
    const float* W2     = (const float*)d_in[7];
    const float* b2     = (const float*)d_in[8];
    const float* w3s    = (const float*)d_in[9];
    const float* w3l    = (const float*)d_in[10];
    const float* w3c    = (const float*)d_in[11];
    const float* ow     = (const float*)d_in[12];
    const float* bias   = (const float*)d_in[13];
    float* out = (float*)d_out;
    int N = in_sizes[13];

    cudaFuncSetAttribute(k_sel, cudaFuncAttributeMaxDynamicSharedMemorySize, SEL_SMEM_BYTES);
    cudaFuncSetAttribute(k_conv, cudaFuncAttributeMaxDynamicSharedMemorySize, CC * 18 * 4);

    k_zero<<<1, 320>>>();
    k_gb<<<LL * BB, 128>>>(gt, gw);

    int chunks = (N + 63) / 64;
    k_sel<<<dim3(chunks, 3), 256, SEL_SMEM_BYTES>>>(coords, W1, b1, W2, b2, w3s, w3l, w3c, N);

    k_scan<<<1, 512>>>();
    k_scatter<<<(N + 255) / 256, 256>>>(N);

    k_conv<<<dim3(8, BB, LL), 256, CC * 18 * 4>>>(lt, cw);

    k_sampf<<<chunks, 256>>>(ow, bias, out, N, chunks, (out_size > 4 * N) ? 1 : 0);
}

// round 7
// speedup vs baseline: 2.5110x; 1.3278x over previous
#include <cuda_runtime.h>

#define LL 12
#define BB 4
#define CC 768
#define HWN 256
#define DD 128
#define NMAX 30000
#define NCELL 289

typedef unsigned long long u64;

// ---------------- device scratch (no allocations allowed) ----------------
__device__ float g_feat[LL * BB * HWN * DD];     // [l][b][hw][d]
__device__ float g_sel_layer[NMAX * LL];
__device__ float g_sel_scale[NMAX];
__device__ float g_corner[NMAX * 4];             // x0f, y0f, wx, wy
__device__ float g_gb[LL * BB * DD];
__device__ float g_ent_part[2048];
__device__ float g_sq_part[2048];
__device__ int   g_cell[NMAX];
__device__ int   g_cellcnt[NCELL];
__device__ int   g_celloff[NCELL + 1];
__device__ int   g_cellfill[NCELL];
__device__ int   g_order[NMAX];

// ---------------- f32x2 packed helpers ----------------
__device__ __forceinline__ u64 pk2(float lo, float hi) {
    u64 r; asm("mov.b64 %0, {%1,%2};" : "=l"(r) : "f"(lo), "f"(hi)); return r;
}
__device__ __forceinline__ u64 ffma2(u64 a, u64 b, u64 c) {
    u64 d; asm("fma.rn.f32x2 %0, %1, %2, %3;" : "=l"(d) : "l"(a), "l"(b), "l"(c)); return d;
}
__device__ __forceinline__ u64 add2(u64 a, u64 b) {
    u64 d; asm("add.rn.f32x2 %0, %1, %2;" : "=l"(d) : "l"(a), "l"(b)); return d;
}
__device__ __forceinline__ float2 up2(u64 v) {
    float2 f; asm("mov.b64 {%0,%1}, %2;" : "=f"(f.x), "=f"(f.y) : "l"(v)); return f;
}
__device__ __forceinline__ float gelu_exact(float x) {
    return 0.5f * x * (1.0f + erff(x * 0.70710678118654752440f));
}
__device__ __forceinline__ float wred(float v) {
#pragma unroll
    for (int o = 16; o; o >>= 1) v += __shfl_xor_sync(0xffffffffu, v, o);
    return v;
}
__device__ __forceinline__ u64 wred2(u64 v) {
#pragma unroll
    for (int o = 16; o; o >>= 1) v = add2(v, __shfl_xor_sync(0xffffffffu, v, o));
    return v;
}

// ---------------- K0: zero bin counters ----------------
__global__ void k_zero() {
    int t = threadIdx.x;
    if (t < NCELL) { g_cellcnt[t] = 0; g_cellfill[t] = 0; }
}

// ---------------- K1: gb[l,b,d] = sum_c gt[l,b,c] * gw[l,d,c] ----------------
__global__ void k_gb(const float* __restrict__ gt, const float* __restrict__ gw) {
    __shared__ float gts[CC];
    int lb = blockIdx.x;
    for (int i = threadIdx.x; i < CC; i += blockDim.x) gts[i] = gt[lb * CC + i];
    __syncthreads();
    int d = threadIdx.x;
    int l = lb >> 2;
    const float4* w4 = (const float4*)(gw + (size_t)(l * DD + d) * CC);
    const float4* t4 = (const float4*)gts;
    float acc = 0.f;
#pragma unroll 8
    for (int c4 = 0; c4 < CC / 4; c4++) {
        float4 w = w4[c4];
        float4 t = t4[c4];
        acc += w.x * t.x + w.y * t.y + w.z * t.z + w.w * t.w;
    }
    g_gb[lb * DD + d] = acc;
}

// ---------------- K2: selector MLPs (3 heads), 64 points per block ----------------
// smem: Wbuf double-buffer (2 x 16 x 128) | pe [64][192] (later h2 [64][132]) | h1 [64][128]
#define SELW_CH   16
#define SELW_F    (SELW_CH * DD)            // 2048 floats per chunk
#define SEL_PE_OFF (2 * SELW_F)             // 4096
#define SEL_H1_OFF (SEL_PE_OFF + 64 * 192)  // 4096 + 12288
#define SEL_SMEM_F (SEL_H1_OFF + 64 * DD)   // + 8192 = 24576 floats
#define SEL_SMEM_BYTES (SEL_SMEM_F * 4)     // 98304 bytes

__device__ __forceinline__ void ldchunk(float* dst, const float* src, int tid) {
    // 16*128 floats = 512 float4, 256 threads -> 2 each
    float4* d4 = (float4*)dst;
    const float4* s4 = (const float4*)src;
    d4[tid]       = s4[tid];
    d4[tid + 256] = s4[tid + 256];
}

__global__ void __launch_bounds__(256, 2) k_sel(
                      const float* __restrict__ coords,
                      const float* __restrict__ W1, const float* __restrict__ b1,
                      const float* __restrict__ W2, const float* __restrict__ b2,
                      const float* __restrict__ w3s, const float* __restrict__ w3l,
                      const float* __restrict__ w3c, int N) {
    extern __shared__ float sm[];
    float* Wb   = sm;                 // 2 chunks of [16][128]
    float* peh2 = sm + SEL_PE_OFF;    // pe [64][192], later h2 [64][132]
    float* h1   = sm + SEL_H1_OFF;    // [64][128]
    __shared__ float redbuf[8];

    const int head = blockIdx.y;
    const int base = blockIdx.x * 64;
    const int tid = threadIdx.x;

    // positional encoding
    for (int idx = tid; idx < 64 * 192; idx += 256) {
        int p = idx / 192, i = idx - p * 192;
        int n = base + p;
        float v = 0.f;
        if (n < N) {
            int c = i >> 6;
            int t = i & 63;
            int k = t & 31;
            float f = 3.14159265358979323846f * exp2f((float)k * (8.0f / 31.0f));
            float ang = coords[n * 3 + c] * f;
            v = (t < 32) ? sinf(ang) : cosf(ang);
        }
        peh2[idx] = v;
    }

    const int tx = tid & 31, ty = tid >> 5;
    const int j0 = tx * 4, p0 = ty * 8;

    const float* W1p = W1 + head * 192 * DD;
    ldchunk(Wb, W1p, tid);
    __syncthreads();

    u64 acc0[8], acc1[8];
#pragma unroll
    for (int p = 0; p < 8; p++) { acc0[p] = 0ULL; acc1[p] = 0ULL; }

    // GEMM1: [64 x 192] @ [192 x 128], W streamed in 12 chunks of 16 rows
    for (int ch = 0; ch < 12; ch++) {
        const float* cur = Wb + (ch & 1) * SELW_F;
        if (ch + 1 < 12)
            ldchunk(Wb + ((ch + 1) & 1) * SELW_F, W1p + (ch + 1) * SELW_F, tid);
        int ibase = ch * SELW_CH;
#pragma unroll
        for (int i = 0; i < SELW_CH; i += 4) {
            float4 pr[8];
#pragma unroll
            for (int p = 0; p < 8; p++)
                pr[p] = *(const float4*)&peh2[(p0 + p) * 192 + ibase + i];
#pragma unroll
            for (int ii = 0; ii < 4; ii++) {
                float4 w = *(const float4*)&cur[(i + ii) * DD + j0];
                u64 w01 = pk2(w.x, w.y), w23 = pk2(w.z, w.w);
#pragma unroll
                for (int p = 0; p < 8; p++) {
                    float pv = (ii == 0) ? pr[p].x : (ii == 1) ? pr[p].y : (ii == 2) ? pr[p].z : pr[p].w;
                    u64 pv2 = pk2(pv, pv);
                    acc0[p] = ffma2(pv2, w01, acc0[p]);
                    acc1[p] = ffma2(pv2, w23, acc1[p]);
                }
            }
        }
        __syncthreads();
    }
    {
        float4 bv = *(const float4*)&b1[head * DD + j0];
#pragma unroll
        for (int p = 0; p < 8; p++) {
            float2 a01 = up2(acc0[p]);
            float2 a23 = up2(acc1[p]);
            float4 h;
            h.x = gelu_exact(a01.x + bv.x);
            h.y = gelu_exact(a01.y + bv.y);
            h.z = gelu_exact(a23.x + bv.z);
            h.w = gelu_exact(a23.y + bv.w);
            *(float4*)&h1[(p0 + p) * DD + j0] = h;
        }
    }
    __syncthreads();

    const float* W2p = W2 + head * DD * DD;
    ldchunk(Wb, W2p, tid);
    __syncthreads();

#pragma unroll
    for (int p = 0; p < 8; p++) { acc0[p] = 0ULL; acc1[p] = 0ULL; }
    // GEMM2: [64 x 128] @ [128 x 128], W streamed in 8 chunks
    for (int ch = 0; ch < 8; ch++) {
        const float* cur = Wb + (ch & 1) * SELW_F;
        if (ch + 1 < 8)
            ldchunk(Wb + ((ch + 1) & 1) * SELW_F, W2p + (ch + 1) * SELW_F, tid);
        int ibase = ch * SELW_CH;
#pragma unroll
        for (int i = 0; i < SELW_CH; i += 4) {
            float4 pr[8];
#pragma unroll
            for (int p = 0; p < 8; p++)
                pr[p] = *(const float4*)&h1[(p0 + p) * DD + ibase + i];
#pragma unroll
            for (int ii = 0; ii < 4; ii++) {
                float4 w = *(const float4*)&cur[(i + ii) * DD + j0];
                u64 w01 = pk2(w.x, w.y), w23 = pk2(w.z, w.w);
#pragma unroll
                for (int p = 0; p < 8; p++) {
                    float pv = (ii == 0) ? pr[p].x : (ii == 1) ? pr[p].y : (ii == 2) ? pr[p].z : pr[p].w;
                    u64 pv2 = pk2(pv, pv);
                    acc0[p] = ffma2(pv2, w01, acc0[p]);
                    acc1[p] = ffma2(pv2, w23, acc1[p]);
                }
            }
        }
        __syncthreads();
    }
    {
        float4 bv = *(const float4*)&b2[head * DD + j0];
#pragma unroll
        for (int p = 0; p < 8; p++) {
            float2 a01 = up2(acc0[p]);
            float2 a23 = up2(acc1[p]);
            float4 h;
            h.x = gelu_exact(a01.x + bv.x);
            h.y = gelu_exact(a01.y + bv.y);
            h.z = gelu_exact(a23.x + bv.z);
            h.w = gelu_exact(a23.y + bv.w);
            *(float4*)&peh2[(p0 + p) * 132 + j0] = h;  // h2 tile over pe area
        }
    }
    __syncthreads();

    // phase3: one thread per point
    float redv = 0.f;
    if (tid < 64) {
        int n = base + tid;
        if (n < N) {
            const float* h2 = &peh2[tid * 132];
            if (head == 0) {
                float o0 = 0.f, o1 = 0.f;
                for (int j = 0; j < DD; j++) {
                    float h = h2[j];
                    o0 += h * w3s[j * 2 + 0];
                    o1 += h * w3s[j * 2 + 1];
                }
                float sx = tanhf(o0), sy = tanhf(o1);
                float xf = (sx + 1.f) * 8.f - 0.5f;
                float yf = (sy + 1.f) * 8.f - 0.5f;
                float x0 = floorf(xf), y0 = floorf(yf);
                g_corner[n * 4 + 0] = x0;
                g_corner[n * 4 + 1] = y0;
                g_corner[n * 4 + 2] = xf - x0;
                g_corner[n * 4 + 3] = yf - y0;
                int cell = ((int)y0 + 1) * 17 + ((int)x0 + 1);
                g_cell[n] = cell;
                atomicAdd(&g_cellcnt[cell], 1);
            } else if (head == 1) {
                float o[12];
#pragma unroll
                for (int t = 0; t < 12; t++) o[t] = 0.f;
                for (int j = 0; j < DD; j++) {
                    float h = h2[j];
#pragma unroll
                    for (int t = 0; t < 12; t++) o[t] += h * w3l[j * 12 + t];
                }
                float mx = o[0];
#pragma unroll
                for (int t = 1; t < 12; t++) mx = fmaxf(mx, o[t]);
                float s = 0.f;
#pragma unroll
                for (int t = 0; t < 12; t++) { o[t] = expf(o[t] - mx); s += o[t]; }
                float inv = 1.f / s;
                float ent = 0.f;
#pragma unroll
                for (int t = 0; t < 12; t++) {
                    float pr = o[t] * inv;
                    g_sel_layer[n * 12 + t] = pr;
                    ent += logf(pr + 1e-8f) * pr;
                }
                redv = ent;
            } else {
                float o0 = 0.f;
                for (int j = 0; j < DD; j++) o0 += h2[j] * w3c[j];
                float s = 1.f / (1.f + expf(-o0));
                g_sel_scale[n] = s;
                float d = s - 0.5f;
                redv = d * d;
            }
        }
    }
    redv = wred(redv);
    if ((tid & 31) == 0) redbuf[tid >> 5] = redv;
    __syncthreads();
    if (tid == 0) {
        float s = 0.f;
#pragma unroll
        for (int w = 0; w < 8; w++) s += redbuf[w];
        if (head == 1) g_ent_part[blockIdx.x] = s;
        else if (head == 2) g_sq_part[blockIdx.x] = s;
    }
}

// ---------------- K2b: prefix sum over cell histogram ----------------
__global__ void k_scan() {
    __shared__ int s[NCELL];
    int t = threadIdx.x;
    if (t < NCELL) s[t] = g_cellcnt[t];
    __syncthreads();
    if (t == 0) {
        int acc = 0;
        for (int i = 0; i < NCELL; i++) { g_celloff[i] = acc; acc += s[i]; }
        g_celloff[NCELL] = acc;
    }
}

// ---------------- K2c: scatter points into cell-sorted order ----------------
__global__ void k_scatter(int N) {
    int n = blockIdx.x * 256 + threadIdx.x;
    if (n < N) {
        int c = g_cell[n];
        int pos = atomicAdd(&g_cellfill[c], 1);
        g_order[g_celloff[c] + pos] = n;
    }
}

// ---------------- K3: feat[l,b,hw,d] = sum_c lt[l,b,c,hw] * cw[l,d,c] ----------------
__global__ void k_conv(const float* __restrict__ lt, const float* __restrict__ cw) {
    extern __shared__ float cws[];  // [768][18]
    int dg = blockIdx.x, b = blockIdx.y, l = blockIdx.z;
    const float* cwp = cw + (size_t)(l * DD + dg * 16) * CC;
    for (int i = threadIdx.x; i < 16 * CC; i += 256) {
        int k = i / CC, c = i - k * CC;
        cws[c * 18 + k] = cwp[i];
    }
    __syncthreads();
    int hw = threadIdx.x;
    const float* ltp = lt + (size_t)(l * BB + b) * CC * HWN;
    u64 acc[8];
#pragma unroll
    for (int k2 = 0; k2 < 8; k2++) acc[k2] = 0ULL;
    for (int c = 0; c < CC; c += 4) {
        float v0 = ltp[(c + 0) * HWN + hw];
        float v1 = ltp[(c + 1) * HWN + hw];
        float v2 = ltp[(c + 2) * HWN + hw];
        float v3 = ltp[(c + 3) * HWN + hw];
#pragma unroll
        for (int cc = 0; cc < 4; cc++) {
            float v = (cc == 0) ? v0 : (cc == 1) ? v1 : (cc == 2) ? v2 : v3;
            u64 v2p = pk2(v, v);
            const u64* wrow = (const u64*)&cws[(c + cc) * 18];
#pragma unroll
            for (int k2 = 0; k2 < 8; k2++)
                acc[k2] = ffma2(v2p, wrow[k2], acc[k2]);
        }
    }
    float* fp = g_feat + ((size_t)(l * BB + b) * HWN + hw) * DD + dg * 16;
#pragma unroll
    for (int k2 = 0; k2 < 8; k2++) ((u64*)fp)[k2] = acc[k2];
}

// ---------------- K4: fused bilinear sample + global path + combine ----------------
__global__ void __launch_bounds__(256, 2) k_sampf(const float* __restrict__ ow,
                                                  const float* __restrict__ bias,
                                                  float* __restrict__ out,
                                                  int N, int npart, int write_reg) {
    __shared__ float gbs[LL * BB * DD];
    for (int i = threadIdx.x; i < LL * BB * DD; i += 256) gbs[i] = g_gb[i];
    __syncthreads();
    int lane = threadIdx.x & 31, warp = threadIdx.x >> 5;

    if (blockIdx.x == 0 && warp == 0 && write_reg) {
        float es = 0.f, ss = 0.f;
        for (int i = lane; i < npart; i += 32) {
            es += g_ent_part[i];
            ss += g_sq_part[i];
        }
        es = wred(es);
        ss = wred(ss);
        if (lane == 0) {
            float reg = (es / (float)N) / 2.4849066497880004f + ss / (float)N;
            out[4 * N] = reg;
        }
    }

    int base = blockIdx.x * 64 + warp * 8;
    for (int j = 0; j < 8; j++) {
        int idx = base + j;
        if (idx >= N) break;
        int n = g_order[idx];
        float4 cd = *(const float4*)&g_corner[n * 4];
        int x0 = (int)cd.x, y0 = (int)cd.y;
        float wx1 = cd.z, wy1 = cd.w, wx0 = 1.f - wx1, wy0 = 1.f - wy1;
        float fx0 = (x0 >= 0) ? wx0 : 0.f;
        float fx1 = (x0 < 15) ? wx1 : 0.f;
        float fy0 = (y0 >= 0) ? wy0 : 0.f;
        float fy1 = (y0 < 15) ? wy1 : 0.f;
        int xc0 = max(x0, 0), xc1 = min(x0 + 1, 15);
        int yc0 = max(y0, 0), yc1 = min(y0 + 1, 15);
        float c00 = fx0 * fy0, c10 = fx1 * fy0, c01 = fx0 * fy1, c11 = fx1 * fy1;
        u64 W00 = pk2(c00, c00), W10 = pk2(c10, c10);
        u64 W01 = pk2(c01, c01), W11 = pk2(c11, c11);
        int p00 = (yc0 * 16 + xc0) << 7, p10 = (yc0 * 16 + xc1) << 7;
        int p01 = (yc1 * 16 + xc0) << 7, p11 = (yc1 * 16 + xc1) << 7;

        float4 o4 = *(const float4*)&ow[n * DD + (lane << 2)];
        u64 oa = pk2(o4.x, o4.y), ob = pk2(o4.z, o4.w);

        float4 wlv0 = *(const float4*)&g_sel_layer[n * 12];
        float4 wlv1 = *(const float4*)&g_sel_layer[n * 12 + 4];
        float4 wlv2 = *(const float4*)&g_sel_layer[n * 12 + 8];
        float wl[12] = {wlv0.x, wlv0.y, wlv0.z, wlv0.w,
                        wlv1.x, wlv1.y, wlv1.z, wlv1.w,
                        wlv2.x, wlv2.y, wlv2.z, wlv2.w};

        // local path: bilinear gather + ow dot
        u64 accL[4];
#pragma unroll
        for (int b = 0; b < 4; b++) accL[b] = 0ULL;
#pragma unroll
        for (int l = 0; l < 12; l++) {
            u64 wl2 = pk2(wl[l], wl[l]);
#pragma unroll
            for (int b = 0; b < 4; b++) {
                const float* f = g_feat + (((size_t)(l * 4 + b)) << 15) + (lane << 2);
                ulonglong2 f00 = *(const ulonglong2*)(f + p00);
                ulonglong2 f10 = *(const ulonglong2*)(f + p10);
                ulonglong2 f01 = *(const ulonglong2*)(f + p01);
                ulonglong2 f11 = *(const ulonglong2*)(f + p11);
                u64 va = ffma2(W00, f00.x,
                         ffma2(W10, f10.x,
                         ffma2(W01, f01.x,
                         ffma2(W11, f11.x, 0ULL))));
                u64 vb = ffma2(W00, f00.y,
                         ffma2(W10, f10.y,
                         ffma2(W01, f01.y,
                         ffma2(W11, f11.y, 0ULL))));
                u64 t = ffma2(va, oa, ffma2(vb, ob, 0ULL));
                accL[b] = ffma2(wl2, t, accL[b]);
            }
        }

        // global path: (sum_l wl * gb[l,b,:]) . ow   (separate loop -> lower peak regs)
        u64 vga[4], vgb[4];
#pragma unroll
        for (int b = 0; b < 4; b++) { vga[b] = 0ULL; vgb[b] = 0ULL; }
#pragma unroll
        for (int l = 0; l < 12; l++) {
            u64 wl2 = pk2(wl[l], wl[l]);
#pragma unroll
            for (int b = 0; b < 4; b++) {
                const ulonglong2* gg = (const ulonglong2*)&gbs[(l * 4 + b) * DD + (lane << 2)];
                ulonglong2 g2 = *gg;
                vga[b] = ffma2(wl2, g2.x, vga[b]);
                vgb[b] = ffma2(wl2, g2.y, vgb[b]);
            }
        }

        float s = g_sel_scale[n];
        float bn = bias[n];
        u64 s2 = pk2(s, s), s1m = pk2(1.f - s, 1.f - s);
        float val[4];
#pragma unroll
        for (int b = 0; b < 4; b++) {
            u64 glob = ffma2(vga[b], oa, ffma2(vgb[b], ob, 0ULL));
            u64 comb = ffma2(s1m, accL[b], ffma2(s2, glob, 0ULL));
            float2 r = up2(comb);
            val[b] = r.x + r.y;
        }
        u64 v01 = wred2(pk2(val[0], val[1]));
        u64 v23 = wred2(pk2(val[2], val[3]));
        if (lane == 0) {
            float2 a = up2(v01), c = up2(v23);
            out[0 * N + n] = a.x * (1.0f / 128.0f) + bn;
            out[1 * N + n] = a.y * (1.0f / 128.0f) + bn;
            out[2 * N + n] = c.x * (1.0f / 128.0f) + bn;
            out[3 * N + n] = c.y * (1.0f / 128.0f) + bn;
        }
    }
}

// ---------------- launch ----------------
extern "C" void kernel_launch(void* const* d_in, const int* in_sizes, int n_in,
                              void* d_out, int out_size) {
    const float* lt     = (const float*)d_in[0];
    const float* gt     = (const float*)d_in[1];
    const float* coords = (const float*)d_in[2];
    const float* cw     = (const float*)d_in[3];
    const float* gw     = (const float*)d_in[4];
    const float* W1     = (const float*)d_in[5];
    const float* b1     = (const float*)d_in[6];
    const float* W2     = (const float*)d_in[7];
    const float* b2     = (const float*)d_in[8];
    const float* w3s    = (const float*)d_in[9];
    const float* w3l    = (const float*)d_in[10];
    const float* w3c    = (const float*)d_in[11];
    const float* ow     = (const float*)d_in[12];
    const float* bias   = (const float*)d_in[13];
    float* out = (float*)d_out;
    int N = in_sizes[13];

    static cudaStream_t s1 = nullptr;
    static cudaEvent_t eFork = nullptr, eJoin = nullptr;
    static bool cfg_done = false;
    if (!cfg_done) {
        cudaStreamCreateWithFlags(&s1, cudaStreamNonBlocking);
        cudaEventCreateWithFlags(&eFork, cudaEventDisableTiming);
        cudaEventCreateWithFlags(&eJoin, cudaEventDisableTiming);
        cudaFuncSetAttribute(k_sel, cudaFuncAttributeMaxDynamicSharedMemorySize, SEL_SMEM_BYTES);
        cudaFuncSetAttribute(k_conv, cudaFuncAttributeMaxDynamicSharedMemorySize, CC * 18 * 4);
        cfg_done = true;
    }

    int chunks = (N + 63) / 64;

    // fork: side stream handles feat conv + global bottleneck
    cudaEventRecord(eFork, 0);
    cudaStreamWaitEvent(s1, eFork, 0);

    k_gb<<<LL * BB, 128, 0, s1>>>(gt, gw);
    k_conv<<<dim3(8, BB, LL), 256, CC * 18 * 4, s1>>>(lt, cw);

    // main stream: selector chain
    k_zero<<<1, 320>>>();
    k_sel<<<dim3(chunks, 3), 256, SEL_SMEM_BYTES>>>(coords, W1, b1, W2, b2, w3s, w3l, w3c, N);
    k_scan<<<1, 512>>>();
    k_scatter<<<(N + 255) / 256, 256>>>(N);

    // join, then fused sample + combine
    cudaEventRecord(eJoin, s1);
    cudaStreamWaitEvent(0, eJoin, 0);

    k_sampf<<<chunks, 256>>>(ow, bias, out, N, chunks, (out_size > 4 * N) ? 1 : 0);
}